// round 15
// baseline (speedup 1.0000x reference)
#include <cuda_runtime.h>
#include <math.h>

// Problem constants (fixed by the dataset)
#define B_   4
#define LP_  256
#define LW_  200
#define D_   768
#define D4_  (D_/4)      // 192 float4 per row
#define NCH_ 37          // word-chunks per batch (15 chunks of 6 + 22 chunks of 5)
#define WMAX_ 6
#define NT_  768         // 4 group-quarters x 192 d-slots

#define MIN_BLOCKS 148
#define MIN_THREADS 1024

__device__ float g_partial_min[MIN_BLOCKS];

// ---------------- global-min partial reduction ----------------
__global__ __launch_bounds__(MIN_THREADS) void partial_min_kernel(
    const float4* __restrict__ x, int n4)
{
    const int stride = MIN_BLOCKS * MIN_THREADS;
    int i = blockIdx.x * MIN_THREADS + threadIdx.x;
    float m = INFINITY;
    if (i < n4) {
        float4 v = x[i];
        m = fminf(fminf(v.x, v.y), fminf(v.z, v.w));
    }
    i += stride;
    if (i < n4) {
        float4 v = x[i];
        m = fminf(m, fminf(fminf(v.x, v.y), fminf(v.z, v.w)));
    }
    #pragma unroll
    for (int off = 16; off > 0; off >>= 1)
        m = fminf(m, __shfl_xor_sync(0xFFFFFFFFu, m, off));

    __shared__ float s[32];
    const int wid = threadIdx.x >> 5;
    const int lid = threadIdx.x & 31;
    if (lid == 0) s[wid] = m;
    __syncthreads();
    if (wid == 0) {
        m = s[lid];
        #pragma unroll
        for (int off = 16; off > 0; off >>= 1)
            m = fminf(m, __shfl_xor_sync(0xFFFFFFFFu, m, off));
        if (lid == 0) g_partial_min[blockIdx.x] = m;
    }
}

__device__ __forceinline__ void fmax4(float4& a, const float4& v) {
    a.x = fmaxf(a.x, v.x); a.y = fmaxf(a.y, v.y);
    a.z = fmaxf(a.z, v.z); a.w = fmaxf(a.w, v.w);
}

// Quarter Q owns groups g = Q + 4u, u = 0..15, contiguous in gflat.
// Groups processed in quads of 4 independent chains -> MLP = 4/thread.
template<int Q>
__device__ __forceinline__ void process_groups(
    const float4* __restrict__ erow,
    const unsigned char* gflat,
    const int* ogoff,           // ordered group offsets (quarter-contiguous)
    float gmin,
    float4* acc)
{
    #pragma unroll
    for (int u0 = 0; u0 < 16; u0 += 4) {
        const int base = 16 * Q + u0;
        int k0 = ogoff[base + 0], e0 = ogoff[base + 1];
        int k1 = ogoff[base + 1], e1 = ogoff[base + 2];
        int k2 = ogoff[base + 2], e2 = ogoff[base + 3];
        int k3 = ogoff[base + 3], e3 = ogoff[base + 4];
        if (Q == 0 && u0 == 0) k0 = e0;     // group 0 touches no word: skip

        float4 t0 = make_float4(gmin, gmin, gmin, gmin);
        float4 t1 = t0, t2 = t0, t3 = t0;

        // 4 independent chains, walked round-robin; all branches are
        // block-uniform (offsets are block-level) -> no divergence.
        while ((k0 < e0) | (k1 < e1) | (k2 < e2) | (k3 < e3)) {
            if (k0 < e0) { fmax4(t0, erow[(size_t)gflat[k0] * D4_]); k0++; }
            if (k1 < e1) { fmax4(t1, erow[(size_t)gflat[k1] * D4_]); k1++; }
            if (k2 < e2) { fmax4(t2, erow[(size_t)gflat[k2] * D4_]); k2++; }
            if (k3 < e3) { fmax4(t3, erow[(size_t)gflat[k3] * D4_]); k3++; }
        }

        // apply: compile-time bits, unconditional (gmin apply is a no-op)
        #pragma unroll
        for (int j = 0; j < WMAX_; j++) {
            if ((Q + 4 * (u0 + 0)) & (1 << j)) fmax4(acc[j], t0);
            if ((Q + 4 * (u0 + 1)) & (1 << j)) fmax4(acc[j], t1);
            if ((Q + 4 * (u0 + 2)) & (1 << j)) fmax4(acc[j], t2);
            if ((Q + 4 * (u0 + 3)) & (1 << j)) fmax4(acc[j], t3);
        }
    }
}

// ---------------- main: masked max-pool, mask-grouped ----------------
__global__ __launch_bounds__(NT_, 1) void word_max_kernel(
    const float* __restrict__ emb,      // [B, Lp, D]
    const int*   __restrict__ p2w,      // [B, Lw, Lp]
    float*       __restrict__ out)      // [B, Lw, D]
{
    __shared__ float4 sacc[2][WMAX_][D4_];      // quarter partials (36.9 KB)
    __shared__ unsigned char pmask[LP_];
    __shared__ unsigned char gflat[LP_];        // pieces, quarter-contiguous
    __shared__ int scount[64];
    __shared__ int scursor[64];
    __shared__ int ogoff[65];
    __shared__ float sgmin;

    const int tid = threadIdx.x;
    const int blk = blockIdx.x;
    const int b   = blk / NCH_;
    const int c   = blk % NCH_;
    const int w0  = (c < 15) ? c * 6 : 90 + (c - 15) * 5;
    const int nw  = (c < 15) ? 6 : 5;

    if (tid < 64) scount[tid] = 0;
    __syncthreads();

    // pass 1: per-piece mask + group counts; warp 8 folds global min
    if (tid < LP_) {
        const int p = tid;
        const int* row = p2w + ((size_t)(b * LW_ + w0)) * LP_ + p;
        unsigned m = 0;
        #pragma unroll
        for (int j = 0; j < WMAX_; j++)
            if (j < nw && row[(size_t)j * LP_] != 0) m |= (1u << j);
        pmask[p] = (unsigned char)m;
        atomicAdd(&scount[m], 1);
    } else if (tid < 288) {
        const int l = tid - 256;
        float m = INFINITY;
        for (int k = l; k < MIN_BLOCKS; k += 32)
            m = fminf(m, g_partial_min[k]);
        #pragma unroll
        for (int off = 16; off > 0; off >>= 1)
            m = fminf(m, __shfl_xor_sync(0xFFFFFFFFu, m, off));
        if (l == 0) sgmin = m;
    }
    __syncthreads();

    // exclusive prefix sum over QUARTER-ORDERED groups:
    // ordered pos i <-> group g(i) = (i>>4) + 4*(i&15)
    if (tid < 32) {
        int g0 = ((2 * tid) >> 4) + 4 * ((2 * tid) & 15);
        int g1 = ((2 * tid + 1) >> 4) + 4 * ((2 * tid + 1) & 15);
        int c0 = scount[g0], c1 = scount[g1];
        int sum = c0 + c1;
        int inc = sum;
        #pragma unroll
        for (int off = 1; off < 32; off <<= 1) {
            int n = __shfl_up_sync(0xFFFFFFFFu, inc, off);
            if (tid >= off) inc += n;
        }
        int base = inc - sum;
        ogoff[2 * tid]     = base;
        ogoff[2 * tid + 1] = base + c0;
        scursor[g0] = base;
        scursor[g1] = base + c0;
        if (tid == 31) ogoff[64] = inc;         // = 256
    }
    __syncthreads();

    // pass 2: scatter piece ids, sorted by ordered group position
    if (tid < LP_) {
        int m = pmask[tid];
        int slot = atomicAdd(&scursor[m], 1);
        gflat[slot] = (unsigned char)tid;
    }
    __syncthreads();

    const float gmin = sgmin;
    const int q  = tid / D4_;        // group-quarter 0..3 (warp-aligned)
    const int dt = tid % D4_;        // float4 slot in D

    float4 acc[WMAX_];
    #pragma unroll
    for (int j = 0; j < WMAX_; j++) acc[j] = make_float4(gmin, gmin, gmin, gmin);

    const float4* erow = reinterpret_cast<const float4*>(emb)
                         + (size_t)b * LP_ * D4_ + dt;

    switch (q) {
        case 0:  process_groups<0>(erow, gflat, ogoff, gmin, acc); break;
        case 1:  process_groups<1>(erow, gflat, ogoff, gmin, acc); break;
        case 2:  process_groups<2>(erow, gflat, ogoff, gmin, acc); break;
        default: process_groups<3>(erow, gflat, ogoff, gmin, acc); break;
    }

    // --- combine quarters: {2,3} -> smem; {0,1} merge; 1 -> smem; 0 final ---
    if (q >= 2) {
        #pragma unroll
        for (int j = 0; j < WMAX_; j++) sacc[q - 2][j][dt] = acc[j];
    }
    __syncthreads();
    if (q < 2) {
        #pragma unroll
        for (int j = 0; j < WMAX_; j++) {
            float4 o = sacc[q][j][dt];
            fmax4(acc[j], o);
        }
        if (q == 1) {
            #pragma unroll
            for (int j = 0; j < WMAX_; j++) sacc[1][j][dt] = acc[j];
        }
    }
    __syncthreads();
    if (q == 0) {
        float4* out4 = reinterpret_cast<float4*>(out)
                       + ((size_t)(b * LW_ + w0)) * D4_ + dt;
        #pragma unroll
        for (int j = 0; j < WMAX_; j++) {
            if (j < nw) {
                float4 o = sacc[1][j][dt];
                fmax4(o, acc[j]);
                out4[(size_t)j * D4_] = o;
            }
        }
    }
}

extern "C" void kernel_launch(void* const* d_in, const int* in_sizes, int n_in,
                              void* d_out, int out_size) {
    const float* emb = (const float*)d_in[0];   // [4,256,768] f32
    const int*   p2w = (const int*)d_in[1];     // [4,200,256] i32
    float*       out = (float*)d_out;           // [4,200,768] f32

    const int n4 = (B_ * LP_ * D_) / 4;         // 196608
    partial_min_kernel<<<MIN_BLOCKS, MIN_THREADS>>>((const float4*)emb, n4);
    word_max_kernel<<<B_ * NCH_, NT_>>>(emb, p2w, out);
}